// round 4
// baseline (speedup 1.0000x reference)
#include <cuda_runtime.h>
#include <mma.h>
#include <math.h>
using namespace nvcuda;

// Problem dims
#define Bb 16
#define Ss 64
#define Rr 6
#define Ll 24
#define Dd 128
#define Hh 256
#define BS 1024      // B*S
#define NSEQ 6144    // B*S*R

// ---------------- scratch (device globals; no allocations allowed) ----------------
__device__ float g_Wbig[4 * 256 * 384];   // [group][j][k]; k<128 x-part, k>=128 h-part
__device__ float g_xw_intra[BS * 768];
__device__ float g_hA[NSEQ * Hh];
__device__ float g_hB[NSEQ * Hh];
__device__ float g_his_last[NSEQ * Hh];
__device__ float g_intra_h[BS * Hh];
__device__ float g_Mrv[NSEQ * 384];
__device__ float g_mpv[BS * 384];
__device__ float g_hp[BS * 288];
__device__ float g_qi[BS * Hh];
__device__ float g_ki[NSEQ * Hh];
__device__ float g_vi[NSEQ * Hh];
__device__ float g_oi[BS * Hh];
__device__ float g_vv[BS * Hh];
__device__ float g_qh[BS * Hh];
__device__ float g_kh[BS * Hh];
__device__ float g_vhp[BS * Hh];
__device__ float g_oh[BS * Hh];
__device__ float g_vh[BS * Hh];
__device__ float g_feat[BS * 640];
__device__ float g_Wq[256 * 384];
__device__ float g_Wk[256 * 384];
__device__ float g_Waq[256 * 128];
__device__ float g_Wak[256 * 128];
__device__ float g_Wav[256 * 288];
__device__ float g_Wln[256 * 640];

__device__ __forceinline__ float sigmoidf_(float x) { return 1.f / (1.f + expf(-x)); }

// ---------------- weight packing ----------------
// g_Wbig[(g*256+j)*384 + k]: g=0 r, g=1 z, g=2 xn (k<128), g=3 hn (k>=128)
__global__ void prep_wbig(const float* __restrict__ w_ih, const float* __restrict__ w_hh,
                          float* __restrict__ Wbig) {
    int idx = blockIdx.x * blockDim.x + threadIdx.x;
    if (idx >= 4 * 256 * 384) return;
    int k = idx % 384;
    int row = idx / 384;
    int g = row >> 8;
    int j = row & 255;
    float v = 0.f;
    if (g == 0) v = (k < 128) ? w_ih[j * 128 + k] : w_hh[j * 256 + (k - 128)];
    else if (g == 1) v = (k < 128) ? w_ih[(256 + j) * 128 + k] : w_hh[(256 + j) * 256 + (k - 128)];
    else if (g == 2) v = (k < 128) ? w_ih[(512 + j) * 128 + k] : 0.f;
    else v = (k < 128) ? 0.f : w_hh[(512 + j) * 256 + (k - 128)];
    Wbig[idx] = v;
}

__global__ void pad_w(const float* __restrict__ src, float* __restrict__ dst,
                      int N, int Ks, int Kd) {
    int idx = blockIdx.x * blockDim.x + threadIdx.x;
    if (idx >= N * Kd) return;
    int n = idx / Kd, k = idx % Kd;
    dst[idx] = (k < Ks) ? src[n * Ks + k] : 0.f;
}

// ---------------- fused tensor-core GRU step ----------------
// Block: 256 thr = 8 warps (wy in {0,1} row-halves, wx = gate group 0..3).
// Tile: 64 rows x (64 j x 4 groups). Phase X: K=128 over x (groups 0,1,2).
// Phase H: K=256 over h_prev (groups 0,1,3). Gating epilogue in-kernel.
__global__ void __launch_bounds__(256) gru_step_tc(
    const float* __restrict__ x,           // offset to step t, row stride Ll*Dd
    int t,
    const float* __restrict__ Wbig,
    const float* __restrict__ b_ih, const float* __restrict__ b_hh,
    const int* __restrict__ lenp,
    const float* __restrict__ h_prev, float* __restrict__ h_out,
    float* __restrict__ his_last)
{
    __shared__ float smem[64 * 36 + 256 * 36];   // As + Bs; Cs aliases (32*260 fits)
    float* As = smem;                  // [64][36]
    float* Bs = smem + 64 * 36;        // [256][36], row c = g*64+u
    float* Cs = smem;                  // [32][260]

    const int i0 = blockIdx.x * 64;
    const int j0 = blockIdx.y * 64;
    const int tid = threadIdx.x;
    const int warp = tid >> 5;
    const int wy = warp >> 2, wx = warp & 3;
    const int XSTR = Ll * Dd;

    wmma::fragment<wmma::accumulator, 16, 16, 8, float> acc[2][4];
#pragma unroll
    for (int a = 0; a < 2; a++)
#pragma unroll
        for (int b = 0; b < 4; b++) wmma::fill_fragment(acc[a][b], 0.f);

    // ---- Phase X: K=128 over x; active groups 0,1,2
    for (int k0 = 0; k0 < 128; k0 += 32) {
#pragma unroll
        for (int it = 0; it < 2; it++) {
            int idx = tid + it * 256;
            int r = idx >> 3, k4 = (idx & 7) << 2;
            float4 v = *(const float4*)(x + (size_t)(i0 + r) * XSTR + k0 + k4);
            *(float4*)(As + r * 36 + k4) = v;
        }
#pragma unroll
        for (int it = 0; it < 6; it++) {           // 192 active rows
            int idx = tid + it * 256;
            int c = idx >> 3, k4 = (idx & 7) << 2;
            int g = c >> 6, u = c & 63;
            float4 v = *(const float4*)(Wbig + (size_t)((g << 8) + j0 + u) * 384 + k0 + k4);
            *(float4*)(Bs + c * 36 + k4) = v;
        }
        __syncthreads();
        if (wx != 3) {
#pragma unroll
            for (int kk = 0; kk < 32; kk += 8) {
                wmma::fragment<wmma::matrix_a, 16, 16, 8, wmma::precision::tf32, wmma::row_major> af[2];
                wmma::fragment<wmma::matrix_b, 16, 16, 8, wmma::precision::tf32, wmma::col_major> bf[4];
#pragma unroll
                for (int fy = 0; fy < 2; fy++) {
                    wmma::load_matrix_sync(af[fy], As + (wy * 32 + fy * 16) * 36 + kk, 36);
#pragma unroll
                    for (int e = 0; e < af[fy].num_elements; e++)
                        af[fy].x[e] = wmma::__float_to_tf32(af[fy].x[e]);
                }
#pragma unroll
                for (int fx = 0; fx < 4; fx++) {
                    wmma::load_matrix_sync(bf[fx], Bs + (wx * 64 + fx * 16) * 36 + kk, 36);
#pragma unroll
                    for (int e = 0; e < bf[fx].num_elements; e++)
                        bf[fx].x[e] = wmma::__float_to_tf32(bf[fx].x[e]);
                }
#pragma unroll
                for (int fy = 0; fy < 2; fy++)
#pragma unroll
                    for (int fx = 0; fx < 4; fx++)
                        wmma::mma_sync(acc[fy][fx], af[fy], bf[fx], acc[fy][fx]);
            }
        }
        __syncthreads();
    }

    // ---- Phase H: K=256 over h_prev; active groups 0,1,3
    if (t > 0) {
        for (int k0 = 0; k0 < 256; k0 += 32) {
#pragma unroll
            for (int it = 0; it < 2; it++) {
                int idx = tid + it * 256;
                int r = idx >> 3, k4 = (idx & 7) << 2;
                float4 v = *(const float4*)(h_prev + (size_t)(i0 + r) * 256 + k0 + k4);
                *(float4*)(As + r * 36 + k4) = v;
            }
#pragma unroll
            for (int it = 0; it < 6; it++) {       // 192 active rows mapped to groups {0,1,3}
                int idx = tid + it * 256;
                int c = idx >> 3, k4 = (idx & 7) << 2;
                int g = (c < 128) ? (c >> 6) : 3;
                int u = c & 63;
                float4 v = *(const float4*)(Wbig + (size_t)((g << 8) + j0 + u) * 384 + 128 + k0 + k4);
                *(float4*)(Bs + ((g << 6) + u) * 36 + k4) = v;
            }
            __syncthreads();
            if (wx != 2) {
#pragma unroll
                for (int kk = 0; kk < 32; kk += 8) {
                    wmma::fragment<wmma::matrix_a, 16, 16, 8, wmma::precision::tf32, wmma::row_major> af[2];
                    wmma::fragment<wmma::matrix_b, 16, 16, 8, wmma::precision::tf32, wmma::col_major> bf[4];
#pragma unroll
                    for (int fy = 0; fy < 2; fy++) {
                        wmma::load_matrix_sync(af[fy], As + (wy * 32 + fy * 16) * 36 + kk, 36);
#pragma unroll
                        for (int e = 0; e < af[fy].num_elements; e++)
                            af[fy].x[e] = wmma::__float_to_tf32(af[fy].x[e]);
                    }
#pragma unroll
                    for (int fx = 0; fx < 4; fx++) {
                        wmma::load_matrix_sync(bf[fx], Bs + (wx * 64 + fx * 16) * 36 + kk, 36);
#pragma unroll
                        for (int e = 0; e < bf[fx].num_elements; e++)
                            bf[fx].x[e] = wmma::__float_to_tf32(bf[fx].x[e]);
                    }
#pragma unroll
                    for (int fy = 0; fy < 2; fy++)
#pragma unroll
                        for (int fx = 0; fx < 4; fx++)
                            wmma::mma_sync(acc[fy][fx], af[fy], bf[fx], acc[fy][fx]);
                }
            }
            __syncthreads();
        }
    }

    // ---- gating epilogue, two row-half passes through Cs[32][260]
    for (int pass = 0; pass < 2; pass++) {
        __syncthreads();
        if (wy == pass) {
#pragma unroll
            for (int fy = 0; fy < 2; fy++)
#pragma unroll
                for (int fx = 0; fx < 4; fx++)
                    wmma::store_matrix_sync(Cs + (fy * 16) * 260 + wx * 64 + fx * 16,
                                            acc[fy][fx], 260, wmma::mem_row_major);
        }
        __syncthreads();
#pragma unroll
        for (int it = 0; it < 2; it++) {
            int idx = tid + it * 256;           // 512 float4 slots: 32 rows x 16
            int row = idx >> 4;
            int q = (idx & 15) << 2;
            int gi = i0 + pass * 32 + row;
            int j = j0 + q;
            float4 aR  = *(float4*)(Cs + row * 260 + q);
            float4 aZ  = *(float4*)(Cs + row * 260 + 64 + q);
            float4 aXN = *(float4*)(Cs + row * 260 + 128 + q);
            float4 aHN = *(float4*)(Cs + row * 260 + 192 + q);
            float4 bir = *(const float4*)(b_ih + j);
            float4 biz = *(const float4*)(b_ih + 256 + j);
            float4 bin = *(const float4*)(b_ih + 512 + j);
            float4 bhr = *(const float4*)(b_hh + j);
            float4 bhz = *(const float4*)(b_hh + 256 + j);
            float4 bhn = *(const float4*)(b_hh + 512 + j);
            float4 hp = make_float4(0.f, 0.f, 0.f, 0.f);
            if (t > 0) hp = *(const float4*)(h_prev + (size_t)gi * 256 + j);
            float4 h;
            {
                float r = sigmoidf_(aR.x + bir.x + bhr.x);
                float z = sigmoidf_(aZ.x + biz.x + bhz.x);
                float n = tanhf(aXN.x + bin.x + r * (aHN.x + bhn.x));
                h.x = (1.f - z) * n + z * hp.x;
            }
            {
                float r = sigmoidf_(aR.y + bir.y + bhr.y);
                float z = sigmoidf_(aZ.y + biz.y + bhz.y);
                float n = tanhf(aXN.y + bin.y + r * (aHN.y + bhn.y));
                h.y = (1.f - z) * n + z * hp.y;
            }
            {
                float r = sigmoidf_(aR.z + bir.z + bhr.z);
                float z = sigmoidf_(aZ.z + biz.z + bhz.z);
                float n = tanhf(aXN.z + bin.z + r * (aHN.z + bhn.z));
                h.z = (1.f - z) * n + z * hp.z;
            }
            {
                float r = sigmoidf_(aR.w + bir.w + bhr.w);
                float z = sigmoidf_(aZ.w + biz.w + bhz.w);
                float n = tanhf(aXN.w + bin.w + r * (aHN.w + bhn.w));
                h.w = (1.f - z) * n + z * hp.w;
            }
            *(float4*)(h_out + (size_t)gi * 256 + j) = h;
            if (lenp[gi] == t + 1)
                *(float4*)(his_last + (size_t)gi * 256 + j) = h;
        }
        __syncthreads();
    }
}

// ---------------- tf32 tensor-core GEMM: C[M,N] = A[M,K] @ W[N,K]^T (+bias) --------
__global__ void __launch_bounds__(256) gemm_tc(
    int M, int N, int K,
    const float* __restrict__ A, int lda,
    const float* __restrict__ W, int ldw,
    const float* __restrict__ bias,
    float* __restrict__ C, int ldc)
{
    __shared__ float smem[128 * 68];
    float* As = smem;
    float* Bs = smem + 128 * 40;

    int i0 = blockIdx.x * 128, n0 = blockIdx.y * 64;
    int tid = threadIdx.x;
    int warp = tid >> 5;
    int wy = warp >> 1, wx = warp & 1;

    wmma::fragment<wmma::accumulator, 16, 16, 8, float> acc[2][2];
#pragma unroll
    for (int a = 0; a < 2; a++)
#pragma unroll
        for (int b = 0; b < 2; b++) wmma::fill_fragment(acc[a][b], 0.f);

    for (int k0 = 0; k0 < K; k0 += 32) {
#pragma unroll
        for (int it = 0; it < 4; it++) {
            int idx = tid + it * 256;
            int r = idx >> 3, k4 = (idx & 7) << 2;
            float4 v = make_float4(0.f, 0.f, 0.f, 0.f);
            int gi = i0 + r;
            if (gi < M) v = *(const float4*)(A + (size_t)gi * lda + k0 + k4);
            *(float4*)(As + r * 40 + k4) = v;
        }
#pragma unroll
        for (int it = 0; it < 2; it++) {
            int idx = tid + it * 256;
            int n = idx >> 3, k4 = (idx & 7) << 2;
            float4 v = *(const float4*)(W + (size_t)(n0 + n) * ldw + k0 + k4);
            *(float4*)(Bs + n * 40 + k4) = v;
        }
        __syncthreads();
#pragma unroll
        for (int kk = 0; kk < 32; kk += 8) {
            wmma::fragment<wmma::matrix_a, 16, 16, 8, wmma::precision::tf32, wmma::row_major> af[2];
            wmma::fragment<wmma::matrix_b, 16, 16, 8, wmma::precision::tf32, wmma::col_major> bf[2];
#pragma unroll
            for (int fy = 0; fy < 2; fy++) {
                wmma::load_matrix_sync(af[fy], As + (wy * 32 + fy * 16) * 40 + kk, 40);
#pragma unroll
                for (int e = 0; e < af[fy].num_elements; e++)
                    af[fy].x[e] = wmma::__float_to_tf32(af[fy].x[e]);
            }
#pragma unroll
            for (int fx = 0; fx < 2; fx++) {
                wmma::load_matrix_sync(bf[fx], Bs + (wx * 32 + fx * 16) * 40 + kk, 40);
#pragma unroll
                for (int e = 0; e < bf[fx].num_elements; e++)
                    bf[fx].x[e] = wmma::__float_to_tf32(bf[fx].x[e]);
            }
#pragma unroll
            for (int fy = 0; fy < 2; fy++)
#pragma unroll
                for (int fx = 0; fx < 2; fx++)
                    wmma::mma_sync(acc[fy][fx], af[fy], bf[fx], acc[fy][fx]);
        }
        __syncthreads();
    }

    float* Cs = smem;
#pragma unroll
    for (int fy = 0; fy < 2; fy++)
#pragma unroll
        for (int fx = 0; fx < 2; fx++)
            wmma::store_matrix_sync(Cs + (wy * 32 + fy * 16) * 68 + wx * 32 + fx * 16,
                                    acc[fy][fx], 68, wmma::mem_row_major);
    __syncthreads();
#pragma unroll
    for (int it = 0; it < 8; it++) {
        int idx = tid + it * 256;
        int r = idx >> 4, c4 = (idx & 15) << 2;
        int gi = i0 + r;
        if (gi >= M) continue;
        float4 v = *(float4*)(Cs + r * 68 + c4);
        if (bias) {
            v.x += bias[n0 + c4];     v.y += bias[n0 + c4 + 1];
            v.z += bias[n0 + c4 + 2]; v.w += bias[n0 + c4 + 3];
        }
        *(float4*)(C + (size_t)gi * ldc + n0 + c4) = v;
    }
}

// ---------------- fused intra GRU ----------------
__global__ void __launch_bounds__(768) intra_gru(
    const float* __restrict__ xw_intra,
    const float* __restrict__ w_hh,
    const float* __restrict__ b_ih, const float* __restrict__ b_hh,
    float* __restrict__ intra_h)
{
    int b = blockIdx.x;
    int tid = threadIdx.x;
    __shared__ float h_sh[256];
    __shared__ float gh_sh[768];
    if (tid < 256) h_sh[tid] = 0.f;
    __syncthreads();
    const float4* w4 = (const float4*)(w_hh + (size_t)tid * 256);
    for (int t = 0; t < Ss; t++) {
        float acc = 0.f;
        const float4* h4 = (const float4*)h_sh;
#pragma unroll 16
        for (int k = 0; k < 64; k++) {
            float4 w = w4[k];
            float4 h = h4[k];
            acc += w.x * h.x + w.y * h.y + w.z * h.z + w.w * h.w;
        }
        gh_sh[tid] = acc;
        __syncthreads();
        if (tid < 256) {
            const float* xwrow = xw_intra + ((size_t)b * Ss + t) * 768;
            float r = sigmoidf_(xwrow[tid] + b_ih[tid] + gh_sh[tid] + b_hh[tid]);
            float z = sigmoidf_(xwrow[256 + tid] + b_ih[256 + tid] + gh_sh[256 + tid] + b_hh[256 + tid]);
            float n = tanhf(xwrow[512 + tid] + b_ih[512 + tid] + r * (gh_sh[512 + tid] + b_hh[512 + tid]));
            float hn = (1.f - z) * n + z * h_sh[tid];
            h_sh[tid] = hn;
            intra_h[((size_t)b * Ss + t) * 256 + tid] = hn;
        }
        __syncthreads();
    }
}

// ---------------- builders ----------------
__global__ void build_mrv(const float* __restrict__ inter_r,
                          const float* __restrict__ his_last, float* __restrict__ Mrv) {
    int idx = blockIdx.x * blockDim.x + threadIdx.x;
    if (idx >= NSEQ * 384) return;
    int i = idx / 384, c = idx % 384;
    Mrv[idx] = (c < 256) ? his_last[i * 256 + c] : inter_r[i * 128 + (c - 256)];
}

__global__ void build_mpv(const float* __restrict__ intra_x,
                          const float* __restrict__ intra_h, float* __restrict__ mpv) {
    int idx = blockIdx.x * blockDim.x + threadIdx.x;
    if (idx >= BS * 384) return;
    int i = idx / 384, c = idx % 384;
    float v;
    if (c < 256) v = intra_h[i * 256 + c];
    else if (c < 383) v = intra_x[i * 128 + (c - 256)];
    else v = 0.f;
    mpv[idx] = v;
}

__global__ void build_hp(const float* __restrict__ intra_x,
                         const float* __restrict__ intra_h, float* __restrict__ hp) {
    int idx = blockIdx.x * blockDim.x + threadIdx.x;
    if (idx >= BS * 257) return;
    int i = idx / 257, c = idx % 257;
    hp[i * 288 + c] = (c < 256) ? intra_h[i * 256 + c] : intra_x[i * 128 + 127];
}

__global__ void build_feat(const float* __restrict__ intra_x, const float* __restrict__ wr,
                           const float* __restrict__ vv, const float* __restrict__ vh,
                           const float* __restrict__ intra_h, float* __restrict__ feat) {
    int idx = blockIdx.x * blockDim.x + threadIdx.x;
    if (idx >= BS * 640) return;
    float e0 = expf(wr[0]), e1 = expf(wr[1]);
    float w0 = e0 / (e0 + e1), w1 = 1.f - w0;
    int i = idx / 640, c = idx % 640;
    float v;
    if (c < 256) v = w0 * vv[i * 256 + c] + w1 * vh[i * 256 + c];
    else if (c < 512) v = intra_h[i * 256 + (c - 256)];
    else if (c < 639) v = intra_x[i * 128 + (c - 512)];
    else v = 0.f;
    feat[idx] = v;
}

// ---------------- attention cores ----------------
__global__ void inter_attn(const float* __restrict__ qi, const float* __restrict__ ki,
                           const float* __restrict__ vi, float* __restrict__ oi) {
    int i = blockIdx.x;
    int tid = threadIdx.x;
    __shared__ float p[12];
    if (tid < 12) {
        int h = tid / 6, rr = tid % 6;
        const float* qp = qi + i * 256 + h * 128;
        const float* kp = ki + (i * 6 + rr) * 256 + h * 128;
        float acc = 0.f;
        for (int d = 0; d < 128; d++) acc += qp[d] * kp[d];
        p[tid] = acc * 0.08838834764831843f;
    }
    __syncthreads();
    if (tid < 2) {
        float mx = -1e30f;
        for (int r = 0; r < 6; r++) mx = fmaxf(mx, p[tid * 6 + r]);
        float sum = 0.f;
        for (int r = 0; r < 6; r++) { float e = expf(p[tid * 6 + r] - mx); p[tid * 6 + r] = e; sum += e; }
        float inv = 1.f / sum;
        for (int r = 0; r < 6; r++) p[tid * 6 + r] *= inv;
    }
    __syncthreads();
    for (int dd = tid; dd < 256; dd += 128) {
        int h = dd >> 7;
        float acc = 0.f;
        for (int r = 0; r < 6; r++) acc += p[h * 6 + r] * vi[(i * 6 + r) * 256 + dd];
        oi[i * 256 + dd] = acc;
    }
}

__global__ void intra_attn(const float* __restrict__ qh, const float* __restrict__ kh,
                           const float* __restrict__ vhp, float* __restrict__ oh) {
    int tq = blockIdx.x, head = blockIdx.y, b = blockIdx.z;
    int tid = threadIdx.x;
    __shared__ float p[64];
    __shared__ float invsum;
    const float* qp = qh + (b * 64 + tq) * 256 + head * 128;
    if (tid < 64) {
        float s = 0.f;
        if (tid <= tq) {
            const float* kp = kh + (b * 64 + tid) * 256 + head * 128;
            float acc = 0.f;
            for (int d = 0; d < 128; d++) acc += qp[d] * kp[d];
            s = acc * 0.08838834764831843f;
        }
        p[tid] = s;
    }
    __syncthreads();
    if (tid == 0) {
        float mx = -1e30f;
        for (int k = 0; k <= tq; k++) mx = fmaxf(mx, p[k]);
        float sum = 0.f;
        for (int k = 0; k <= tq; k++) { float e = expf(p[k] - mx); p[k] = e; sum += e; }
        invsum = 1.f / sum;
    }
    __syncthreads();
    float inv = invsum;
    {
        int d = tid;
        float acc = 0.f;
        for (int k = 0; k <= tq; k++) acc += p[k] * vhp[(b * 64 + k) * 256 + head * 128 + d];
        oh[(b * 64 + tq) * 256 + head * 128 + d] = acc * inv;
    }
}

// ---------------- launch ----------------
extern "C" void kernel_launch(void* const* d_in, const int* in_sizes, int n_in,
                              void* d_out, int out_size) {
    const float* intra_x   = (const float*)d_in[0];
    const float* inter_his = (const float*)d_in[1];
    const float* inter_r   = (const float*)d_in[2];
    const int*   inter_len = (const int*)d_in[4];
    const float* w_ih = (const float*)d_in[5];
    const float* w_hh = (const float*)d_in[6];
    const float* b_ih = (const float*)d_in[7];
    const float* b_hh = (const float*)d_in[8];
    const float* iq_w = (const float*)d_in[9];
    const float* iq_b = (const float*)d_in[10];
    const float* ik_w = (const float*)d_in[11];
    const float* ik_b = (const float*)d_in[12];
    const float* iv_w = (const float*)d_in[13];
    const float* iv_b = (const float*)d_in[14];
    const float* io_w = (const float*)d_in[15];
    const float* io_b = (const float*)d_in[16];
    const float* aq_w = (const float*)d_in[17];
    const float* aq_b = (const float*)d_in[18];
    const float* ak_w = (const float*)d_in[19];
    const float* ak_b = (const float*)d_in[20];
    const float* av_w = (const float*)d_in[21];
    const float* av_b = (const float*)d_in[22];
    const float* ao_w = (const float*)d_in[23];
    const float* ao_b = (const float*)d_in[24];
    const float* wr   = (const float*)d_in[25];
    const float* ln_w = (const float*)d_in[26];
    const float* ln_b = (const float*)d_in[27];
    float* out = (float*)d_out;

    float *p_Wbig, *p_xw_intra, *p_hA, *p_hB, *p_his, *p_ih, *p_Mrv, *p_mpv, *p_hp;
    float *p_qi, *p_ki, *p_vi, *p_oi, *p_vv, *p_qh, *p_kh, *p_vhp, *p_oh, *p_vh, *p_feat;
    float *p_Wq, *p_Wk, *p_Waq, *p_Wak, *p_Wav, *p_Wln;
    cudaGetSymbolAddress((void**)&p_Wbig, g_Wbig);
    cudaGetSymbolAddress((void**)&p_xw_intra, g_xw_intra);
    cudaGetSymbolAddress((void**)&p_hA, g_hA);
    cudaGetSymbolAddress((void**)&p_hB, g_hB);
    cudaGetSymbolAddress((void**)&p_his, g_his_last);
    cudaGetSymbolAddress((void**)&p_ih, g_intra_h);
    cudaGetSymbolAddress((void**)&p_Mrv, g_Mrv);
    cudaGetSymbolAddress((void**)&p_mpv, g_mpv);
    cudaGetSymbolAddress((void**)&p_hp, g_hp);
    cudaGetSymbolAddress((void**)&p_qi, g_qi);
    cudaGetSymbolAddress((void**)&p_ki, g_ki);
    cudaGetSymbolAddress((void**)&p_vi, g_vi);
    cudaGetSymbolAddress((void**)&p_oi, g_oi);
    cudaGetSymbolAddress((void**)&p_vv, g_vv);
    cudaGetSymbolAddress((void**)&p_qh, g_qh);
    cudaGetSymbolAddress((void**)&p_kh, g_kh);
    cudaGetSymbolAddress((void**)&p_vhp, g_vhp);
    cudaGetSymbolAddress((void**)&p_oh, g_oh);
    cudaGetSymbolAddress((void**)&p_vh, g_vh);
    cudaGetSymbolAddress((void**)&p_feat, g_feat);
    cudaGetSymbolAddress((void**)&p_Wq, g_Wq);
    cudaGetSymbolAddress((void**)&p_Wk, g_Wk);
    cudaGetSymbolAddress((void**)&p_Waq, g_Waq);
    cudaGetSymbolAddress((void**)&p_Wak, g_Wak);
    cudaGetSymbolAddress((void**)&p_Wav, g_Wav);
    cudaGetSymbolAddress((void**)&p_Wln, g_Wln);

    // weight packing/padding
    prep_wbig<<<(4 * 256 * 384 + 255) / 256, 256>>>(w_ih, w_hh, p_Wbig);
    pad_w<<<(256 * 384 + 255) / 256, 256>>>(iq_w, p_Wq, 256, 383, 384);
    pad_w<<<(256 * 384 + 255) / 256, 256>>>(ik_w, p_Wk, 256, 383, 384);
    pad_w<<<(256 * 128 + 255) / 256, 256>>>(aq_w, p_Waq, 256, 127, 128);
    pad_w<<<(256 * 128 + 255) / 256, 256>>>(ak_w, p_Wak, 256, 127, 128);
    pad_w<<<(256 * 288 + 255) / 256, 256>>>(av_w, p_Wav, 256, 257, 288);
    pad_w<<<(256 * 640 + 255) / 256, 256>>>(ln_w, p_Wln, 256, 639, 640);

    // intra input projection (small, hoisted)
    gemm_tc<<<dim3(8, 12), 256>>>(BS, 768, 128, intra_x, 128, w_ih, 128, nullptr, p_xw_intra, 768);

    // inter GRU: 24 fully-fused tensor-core steps
    for (int t = 0; t < Ll; t++) {
        float* h_out  = (t & 1) ? p_hB : p_hA;
        float* h_prev = (t & 1) ? p_hA : p_hB;
        gru_step_tc<<<dim3(96, 4), 256>>>(inter_his + t * Dd, t, p_Wbig, b_ih, b_hh,
                                          inter_len, h_prev, h_out, p_his);
    }

    // intra GRU: fused, one launch
    intra_gru<<<Bb, 768>>>(p_xw_intra, w_hh, b_ih, b_hh, p_ih);

    // builders
    build_mrv<<<(NSEQ * 384 + 255) / 256, 256>>>(inter_r, p_his, p_Mrv);
    build_mpv<<<(BS * 384 + 255) / 256, 256>>>(intra_x, p_ih, p_mpv);
    build_hp<<<(BS * 257 + 255) / 256, 256>>>(intra_x, p_ih, p_hp);

    // inter MHA
    gemm_tc<<<dim3(8, 4), 256>>>(BS, 256, 384, p_mpv, 384, p_Wq, 384, iq_b, p_qi, 256);
    gemm_tc<<<dim3(48, 4), 256>>>(NSEQ, 256, 384, p_Mrv, 384, p_Wk, 384, ik_b, p_ki, 256);
    gemm_tc<<<dim3(48, 4), 256>>>(NSEQ, 256, 384, p_Mrv, 384, iv_w, 384, iv_b, p_vi, 256);
    inter_attn<<<BS, 128>>>(p_qi, p_ki, p_vi, p_oi);
    gemm_tc<<<dim3(8, 4), 256>>>(BS, 256, 256, p_oi, 256, io_w, 256, io_b, p_vv, 256);

    // intra MHA
    gemm_tc<<<dim3(8, 4), 256>>>(BS, 256, 128, intra_x, 128, p_Waq, 128, aq_b, p_qh, 256);
    gemm_tc<<<dim3(8, 4), 256>>>(BS, 256, 128, intra_x, 128, p_Wak, 128, ak_b, p_kh, 256);
    gemm_tc<<<dim3(8, 4), 256>>>(BS, 256, 288, p_hp, 288, p_Wav, 288, av_b, p_vhp, 256);
    intra_attn<<<dim3(64, 2, 16), 128>>>(p_qh, p_kh, p_vhp, p_oh);
    gemm_tc<<<dim3(8, 4), 256>>>(BS, 256, 256, p_oh, 256, ao_w, 256, ao_b, p_vh, 256);

    // combine + final projection
    build_feat<<<(BS * 640 + 255) / 256, 256>>>(intra_x, wr, p_vv, p_vh, p_ih, p_feat);
    gemm_tc<<<dim3(8, 4), 256>>>(BS, 256, 640, p_feat, 640, p_Wln, 640, ln_b, out, 256);
}